// round 11
// baseline (speedup 1.0000x reference)
#include <cuda_runtime.h>
#include <cuda_fp16.h>
#include <cstdint>

// ---------------------------------------------------------------------------
// SpatialWindowSelfAttention: b=2, img 256x256, C=256, 8 heads x 32, 8x8 windows
// Full fp16 pipeline, fp32 accumulation, mma.sync m16n8k16.
// GEMM1 fuses the f32->f16 conversion of x (no separate cvt pass for x).
// ---------------------------------------------------------------------------

#define IMG        256
#define BATCH      2
#define CDIM       256
#define NTOK       (BATCH * IMG * IMG)      // 131072
#define HEADS      8
#define HD         32
#define WS         64
#define NWIN       2048
#define QKV_DIM    (3 * CDIM)               // 768
#define GK         256

// Scratch (device globals; no allocs allowed)
__device__ __half g_wq [(size_t)QKV_DIM * CDIM];
__device__ __half g_wp [(size_t)CDIM * CDIM];
__device__ __half g_qkv[(size_t)NTOK * QKV_DIM];  // [sel][head][win][tok][hd]
__device__ __half g_y  [(size_t)NTOK * CDIM];     // token-major

// ---------------------------------------------------------------------------
// helpers
// ---------------------------------------------------------------------------
__device__ __forceinline__ uint32_t smem_u32(const void* p) {
    uint32_t a;
    asm("{ .reg .u64 t; cvta.to.shared.u64 t, %1; cvt.u32.u64 %0, t; }" : "=r"(a) : "l"(p));
    return a;
}
__device__ __forceinline__ void cp16(uint32_t s, const void* g) {
    asm volatile("cp.async.cg.shared.global [%0], [%1], 16;\n" :: "r"(s), "l"(g) : "memory");
}
#define CP_COMMIT() asm volatile("cp.async.commit_group;\n" ::: "memory")
template <int N>
__device__ __forceinline__ void cp_wait() {
    asm volatile("cp.async.wait_group %0;\n" :: "n"(N) : "memory");
}
__device__ __forceinline__ void ldsm4(uint32_t& r0, uint32_t& r1, uint32_t& r2,
                                      uint32_t& r3, uint32_t addr) {
    asm volatile("ldmatrix.sync.aligned.m8n8.x4.shared.b16 {%0,%1,%2,%3}, [%4];"
                 : "=r"(r0), "=r"(r1), "=r"(r2), "=r"(r3) : "r"(addr));
}
__device__ __forceinline__ void ldsm4t(uint32_t& r0, uint32_t& r1, uint32_t& r2,
                                       uint32_t& r3, uint32_t addr) {
    asm volatile("ldmatrix.sync.aligned.m8n8.x4.trans.shared.b16 {%0,%1,%2,%3}, [%4];"
                 : "=r"(r0), "=r"(r1), "=r"(r2), "=r"(r3) : "r"(addr));
}
__device__ __forceinline__ void mma_f16(float* d, const uint32_t* a, const uint32_t* b) {
    asm volatile(
        "mma.sync.aligned.m16n8k16.row.col.f32.f16.f16.f32 "
        "{%0,%1,%2,%3},{%4,%5,%6,%7},{%8,%9},{%0,%1,%2,%3};"
        : "+f"(d[0]), "+f"(d[1]), "+f"(d[2]), "+f"(d[3])
        : "r"(a[0]), "r"(a[1]), "r"(a[2]), "r"(a[3]), "r"(b[0]), "r"(b[1]));
}

// ---------------------------------------------------------------------------
// prep: convert f32 -> f16 (RN) — weights only
// ---------------------------------------------------------------------------
__global__ void cvt_half_kernel(const float4* __restrict__ src, uint2* __restrict__ dst, int n4)
{
    for (int i = blockIdx.x * blockDim.x + threadIdx.x; i < n4; i += gridDim.x * blockDim.x) {
        const float4 v = src[i];
        const __half2 h0 = __floats2half2_rn(v.x, v.y);
        const __half2 h1 = __floats2half2_rn(v.z, v.w);
        uint2 u;
        u.x = *(const uint32_t*)&h0;
        u.y = *(const uint32_t*)&h1;
        dst[i] = u;
    }
}

// ---------------------------------------------------------------------------
// fp16 GEMM: C[m][n] = sum_k A[m][k]*B[n][k] + bias[n], fp32 accum.
// 256 threads = 8 warps, 2m x 4n, warp tile 64x32. CTA tile 128x128.
// 3 smem buffers, 2 chunks in flight, one __syncthreads per chunk.
// CVTA:  A is f32 -> fused LDG+cvt+STS into the fp16 A stage.
// OUTHALF: store __half (else float). SCATTER: window-major qkv scatter.
// ---------------------------------------------------------------------------
#define STAGE_B 32768
#define NCHUNK  4
template<int CVTA, int OUTHALF, int SCATTER>
__global__ void __launch_bounds__(256, 2)
gemm_mma_kernel(const void* __restrict__ Av,
                const __half* __restrict__ Bw,
                const float* __restrict__ bias,
                void* __restrict__ Cv, int N)
{
    extern __shared__ char sm[];
    const uint32_t sb = smem_u32(sm);

    const int tid  = threadIdx.x;
    const int lane = tid & 31;
    const int wid  = tid >> 5;
    const int g    = lane >> 2;
    const int t4   = lane & 3;
    const int wm   = (wid & 1) * 64;
    const int wn   = (wid >> 1) * 32;
    const int m0   = blockIdx.y * 128;
    const int n0   = blockIdx.x * 128;

    const char*  Ag   = CVTA ? 0 : (const char*)((const __half*)Av + (size_t)m0 * GK);
    const float* Ag32 = CVTA ? (const float*)Av + (size_t)m0 * GK : 0;
    const char*  Bg   = (const char*)(Bw + (size_t)n0 * GK);

    float acc[4][4][4];
#pragma unroll
    for (int i = 0; i < 4; i++)
#pragma unroll
        for (int j = 0; j < 4; j++)
#pragma unroll
            for (int c = 0; c < 4; c++) acc[i][j][c] = 0.f;

    int rowA[4];
#pragma unroll
    for (int mf = 0; mf < 4; mf++) rowA[mf] = wm + mf * 16 + (lane & 15);
    const int haA = lane >> 4;
    int rowB[2];
#pragma unroll
    for (int p = 0; p < 2; p++) rowB[p] = wn + p * 16 + (lane & 7) + ((lane & 16) ? 8 : 0);
    const int haB = (lane >> 3) & 1;

    // B loader: 128 rows x 8 16B chunks = 1024 units, 4 per thread
    auto load_B = [&](int it, int s) {
        const uint32_t sa = sb + (uint32_t)s * STAGE_B + 16384;
#pragma unroll
        for (int i = 0; i < 4; i++) {
            const int idx = tid + i * 256;
            const int row = idx >> 3, c = idx & 7;
            const uint32_t off = (uint32_t)(row * 128 + ((c ^ (row & 7)) << 4));
            cp16(sa + off, Bg + (size_t)row * (GK * 2) + it * 128 + c * 16);
        }
    };

    // A f16 loader (CVTA=0)
    auto load_A = [&](int it, int s) {
        const uint32_t sa = sb + (uint32_t)s * STAGE_B;
#pragma unroll
        for (int i = 0; i < 4; i++) {
            const int idx = tid + i * 256;
            const int row = idx >> 3, c = idx & 7;
            const uint32_t off = (uint32_t)(row * 128 + ((c ^ (row & 7)) << 4));
            cp16(sa + off, Ag + (size_t)row * (GK * 2) + it * 128 + c * 16);
        }
    };

    // A f32 loader with fused cvt (CVTA=1): 16B-f16 unit = 8 f32 = 32B LDG
    auto load_A_cvt = [&](int it, int s) {
        const uint32_t sa = sb + (uint32_t)s * STAGE_B;
#pragma unroll
        for (int i = 0; i < 4; i++) {
            const int idx = tid + i * 256;
            const int row = idx >> 3, c = idx & 7;
            const float4* src = (const float4*)(Ag32 + (size_t)row * GK + it * 64 + c * 8);
            const float4 f0 = src[0];
            const float4 f1 = src[1];
            const __half2 h0 = __floats2half2_rn(f0.x, f0.y);
            const __half2 h1 = __floats2half2_rn(f0.z, f0.w);
            const __half2 h2 = __floats2half2_rn(f1.x, f1.y);
            const __half2 h3 = __floats2half2_rn(f1.z, f1.w);
            const uint32_t off = (uint32_t)(row * 128 + ((c ^ (row & 7)) << 4));
            asm volatile("st.shared.v4.b32 [%0], {%1,%2,%3,%4};"
                         :: "r"(sa + off),
                            "r"(*(const uint32_t*)&h0), "r"(*(const uint32_t*)&h1),
                            "r"(*(const uint32_t*)&h2), "r"(*(const uint32_t*)&h3)
                         : "memory");
        }
    };

    // prologue: 2 chunks in flight
    if (CVTA) {
        load_A_cvt(0, 0); load_B(0, 0); CP_COMMIT();
        load_A_cvt(1, 1); load_B(1, 1); CP_COMMIT();
    } else {
        load_A(0, 0); load_B(0, 0); CP_COMMIT();
        load_A(1, 1); load_B(1, 1); CP_COMMIT();
    }

#pragma unroll 1
    for (int it = 0; it < NCHUNK; it++) {
        if (it == NCHUNK - 1) cp_wait<0>();
        else                  cp_wait<1>();
        __syncthreads();     // chunk `it` resident (B via cp groups, A via STS+sync)

        if (it + 2 < NCHUNK) {
            const int s2 = (it + 2) % 3;
            if (CVTA) { load_A_cvt(it + 2, s2); } else { load_A(it + 2, s2); }
            load_B(it + 2, s2); CP_COMMIT();
        }

        const uint32_t sa = sb + (uint32_t)(it % 3) * STAGE_B;
#pragma unroll
        for (int s = 0; s < 4; s++) {          // 4 x k16 steps per 64-half chunk
            uint32_t a[4][4], b[4][2];
#pragma unroll
            for (int mf = 0; mf < 4; mf++) {
                const int r = rowA[mf];
                ldsm4(a[mf][0], a[mf][1], a[mf][2], a[mf][3],
                      sa + r * 128 + (((2 * s + haA) ^ (r & 7)) << 4));
            }
#pragma unroll
            for (int p = 0; p < 2; p++) {
                const int r = rowB[p];
                uint32_t r0, r1, r2, r3;
                ldsm4(r0, r1, r2, r3,
                      sa + 16384 + r * 128 + (((2 * s + haB) ^ (r & 7)) << 4));
                b[2 * p][0] = r0; b[2 * p][1] = r1;
                b[2 * p + 1][0] = r2; b[2 * p + 1][1] = r3;
            }
#pragma unroll
            for (int mf = 0; mf < 4; mf++)
#pragma unroll
                for (int nf = 0; nf < 4; nf++)
                    mma_f16(acc[mf][nf], a[mf], b[nf]);
        }
    }

    // epilogue
#pragma unroll
    for (int mf = 0; mf < 4; mf++) {
        const int r0 = m0 + wm + mf * 16 + g;
        const int r1 = r0 + 8;
        size_t tb0 = 0, tb1 = 0;
        if (SCATTER) {
            const int bb0 = r0 >> 16, px0 = r0 & 65535;
            const int win0 = bb0 * 1024 + ((px0 >> 8) >> 3) * 32 + ((px0 & 255) >> 3);
            const int tk0  = (((px0 >> 8) & 7) << 3) + (px0 & 7);
            tb0 = (size_t)win0 * (WS * HD) + tk0 * HD;
            const int bb1 = r1 >> 16, px1 = r1 & 65535;
            const int win1 = bb1 * 1024 + ((px1 >> 8) >> 3) * 32 + ((px1 & 255) >> 3);
            const int tk1  = (((px1 >> 8) & 7) << 3) + (px1 & 7);
            tb1 = (size_t)win1 * (WS * HD) + tk1 * HD;
        }
#pragma unroll
        for (int nf = 0; nf < 4; nf++) {
            const int col = n0 + wn + nf * 8 + 2 * t4;
            const float2 bv = *(const float2*)&bias[col];
            float2 o0, o1;
            o0.x = acc[mf][nf][0] + bv.x;
            o0.y = acc[mf][nf][1] + bv.y;
            o1.x = acc[mf][nf][2] + bv.x;
            o1.y = acc[mf][nf][3] + bv.y;
            if (OUTHALF) {
                __half* C = (__half*)Cv;
                const __half2 h0 = __floats2half2_rn(o0.x, o0.y);
                const __half2 h1 = __floats2half2_rn(o1.x, o1.y);
                if (SCATTER) {
                    const size_t ch = (size_t)(col >> 5) * ((size_t)NWIN * WS * HD) + (col & 31);
                    *(__half2*)&C[ch + tb0] = h0;
                    *(__half2*)&C[ch + tb1] = h1;
                } else {
                    *(__half2*)&C[(size_t)r0 * N + col] = h0;
                    *(__half2*)&C[(size_t)r1 * N + col] = h1;
                }
            } else {
                float* C = (float*)Cv;
                *(float2*)&C[(size_t)r0 * N + col] = o0;
                *(float2*)&C[(size_t)r1 * N + col] = o1;
            }
        }
    }
}

// ---------------------------------------------------------------------------
// Window attention, fp16 tensor cores. Block = (window, head), 128 thr, 4 warps.
// smem: qs/ks/vs 80B-pitch rows; p16 aliases qs+ks (144B pitch); bt table.
// Softmax fully in registers (quad shfl).
// ---------------------------------------------------------------------------
__global__ __launch_bounds__(128, 8)
void attn_kernel(const __half* __restrict__ qkv,
                 const float* __restrict__ bias_table,
                 __half* __restrict__ y)
{
    __shared__ __align__(16) char sraw[15360 + 912];
    const uint32_t base = smem_u32(sraw);
    const uint32_t qsb = base;
    const uint32_t ksb = base + 5120;
    const uint32_t vsb = base + 10240;
    const uint32_t pb  = base;           // alias over qs+ks
    float* bt = (float*)(sraw + 15360);

    const int tid  = threadIdx.x;
    const int lane = tid & 31;
    const int wid  = tid >> 5;
    const int g    = lane >> 2;
    const int t4   = lane & 3;
    const int win  = blockIdx.x;
    const int hh   = blockIdx.y;

    const __half* qg = qkv + ((size_t)(0 * HEADS + hh) * NWIN + win) * (WS * HD);
    const __half* kg = qkv + ((size_t)(1 * HEADS + hh) * NWIN + win) * (WS * HD);
    const __half* vg = qkv + ((size_t)(2 * HEADS + hh) * NWIN + win) * (WS * HD);

#pragma unroll
    for (int i = 0; i < 6; i++) {
        const int idx = tid + i * 128;
        const int sel = idx >> 8;           // 0=q,1=k,2=v
        const int rem = idx & 255;
        const int t   = rem >> 2;
        const int c   = rem & 3;
        const __half* src = (sel == 0 ? qg : sel == 1 ? kg : vg) + t * HD + c * 8;
        const uint32_t dstb = (sel == 0 ? qsb : sel == 1 ? ksb : vsb);
        cp16(dstb + t * 80 + c * 16, src);
    }
    CP_COMMIT();

    for (int i = tid; i < 225; i += 128) bt[i] = bias_table[i * HEADS + hh];
    cp_wait<0>();
    __syncthreads();

    // ---- QK^T ----
    float s[8][4];
#pragma unroll
    for (int j = 0; j < 8; j++)
#pragma unroll
        for (int c = 0; c < 4; c++) s[j][c] = 0.f;

    const int rA  = wid * 16 + (lane & 15);
    const int haA = lane >> 4;
    const int haB = (lane >> 3) & 1;

#pragma unroll
    for (int s2 = 0; s2 < 2; s2++) {
        uint32_t a[4];
        ldsm4(a[0], a[1], a[2], a[3], qsb + rA * 80 + (2 * s2 + haA) * 16);
#pragma unroll
        for (int p = 0; p < 4; p++) {
            const int r = p * 16 + (lane & 7) + ((lane & 16) ? 8 : 0);
            uint32_t b0, b1, b2, b3;
            ldsm4(b0, b1, b2, b3, ksb + r * 80 + (2 * s2 + haB) * 16);
            uint32_t bA[2] = {b0, b1}, bB[2] = {b2, b3};
            mma_f16(s[2 * p], a, bA);
            mma_f16(s[2 * p + 1], a, bB);
        }
    }

    // ---- scale + bias + softmax in regs ----
    const float scale = 0.17677669529663687f;
    const int qlo = wid * 16 + g;
    const int qhi = qlo + 8;
    const int qi0 = qlo >> 3, qj0 = qlo & 7;
    const int qi1 = qhi >> 3, qj1 = qhi & 7;

    float mlo = -1e30f, mhi = -1e30f;
#pragma unroll
    for (int j = 0; j < 8; j++) {
        const int c0 = j * 8 + 2 * t4, c1 = c0 + 1;
        const int ki0 = c0 >> 3, kj0 = c0 & 7;
        const int ki1 = c1 >> 3, kj1 = c1 & 7;
        s[j][0] = s[j][0] * scale + bt[(qi0 - ki0 + 7) * 15 + (qj0 - kj0 + 7)];
        s[j][1] = s[j][1] * scale + bt[(qi0 - ki1 + 7) * 15 + (qj0 - kj1 + 7)];
        s[j][2] = s[j][2] * scale + bt[(qi1 - ki0 + 7) * 15 + (qj1 - kj0 + 7)];
        s[j][3] = s[j][3] * scale + bt[(qi1 - ki1 + 7) * 15 + (qj1 - kj1 + 7)];
        mlo = fmaxf(mlo, fmaxf(s[j][0], s[j][1]));
        mhi = fmaxf(mhi, fmaxf(s[j][2], s[j][3]));
    }
    mlo = fmaxf(mlo, __shfl_xor_sync(0xffffffffu, mlo, 1));
    mlo = fmaxf(mlo, __shfl_xor_sync(0xffffffffu, mlo, 2));
    mhi = fmaxf(mhi, __shfl_xor_sync(0xffffffffu, mhi, 1));
    mhi = fmaxf(mhi, __shfl_xor_sync(0xffffffffu, mhi, 2));

    float slo = 0.f, shi = 0.f;
#pragma unroll
    for (int j = 0; j < 8; j++) {
        s[j][0] = __expf(s[j][0] - mlo);
        s[j][1] = __expf(s[j][1] - mlo);
        s[j][2] = __expf(s[j][2] - mhi);
        s[j][3] = __expf(s[j][3] - mhi);
        slo += s[j][0] + s[j][1];
        shi += s[j][2] + s[j][3];
    }
    slo += __shfl_xor_sync(0xffffffffu, slo, 1);
    slo += __shfl_xor_sync(0xffffffffu, slo, 2);
    shi += __shfl_xor_sync(0xffffffffu, shi, 1);
    shi += __shfl_xor_sync(0xffffffffu, shi, 2);
    const float ilo = 1.f / slo, ihi = 1.f / shi;

    __syncthreads();

    // ---- store P as fp16 (144B pitch) ----
#pragma unroll
    for (int j = 0; j < 8; j++) {
        const int c0 = j * 8 + 2 * t4;
        const __half2 plo = __floats2half2_rn(s[j][0] * ilo, s[j][1] * ilo);
        const __half2 phi = __floats2half2_rn(s[j][2] * ihi, s[j][3] * ihi);
        *(__half2*)(uintptr_t)__cvta_shared_to_generic(pb + qlo * 144 + c0 * 2) = plo;
        *(__half2*)(uintptr_t)__cvta_shared_to_generic(pb + qhi * 144 + c0 * 2) = phi;
    }
    __syncthreads();

    // ---- PV ----
    float o[4][4];
#pragma unroll
    for (int j = 0; j < 4; j++)
#pragma unroll
        for (int c = 0; c < 4; c++) o[j][c] = 0.f;

#pragma unroll
    for (int s2 = 0; s2 < 4; s2++) {
        uint32_t a[4];
        ldsm4(a[0], a[1], a[2], a[3], pb + rA * 144 + (2 * s2 + haA) * 16);
#pragma unroll
        for (int p = 0; p < 2; p++) {
            const int key = 16 * s2 + (lane & 7) + ((lane & 8) ? 8 : 0);
            const int chk = 2 * p + ((lane & 16) ? 1 : 0);
            uint32_t r0, r1, r2, r3;
            ldsm4t(r0, r1, r2, r3, vsb + key * 80 + chk * 16);
            uint32_t bA[2] = {r0, r1}, bB[2] = {r2, r3};
            mma_f16(o[2 * p], a, bA);
            mma_f16(o[2 * p + 1], a, bB);
        }
    }

    // ---- write y (fp16, token-major) ----
    {
        const int bb = win >> 10;
        const int wr = (win >> 5) & 31;
        const int wc = win & 31;
#pragma unroll
        for (int rr = 0; rr < 2; rr++) {
            const int qr = wid * 16 + g + rr * 8;
            const int trw = qr >> 3, tcl = qr & 7;
            const size_t tok = (size_t)bb * (IMG * IMG)
                             + (size_t)(wr * 8 + trw) * IMG + (wc * 8 + tcl);
            __half* dst = &y[tok * CDIM + hh * HD];
#pragma unroll
            for (int j = 0; j < 4; j++) {
                const int col = j * 8 + 2 * t4;
                const __half2 hv = __floats2half2_rn(o[j][rr * 2 + 0], o[j][rr * 2 + 1]);
                *(__half2*)&dst[col] = hv;
            }
        }
    }
}

// ---------------------------------------------------------------------------
extern "C" void kernel_launch(void* const* d_in, const int* in_sizes, int n_in,
                              void* d_out, int out_size)
{
    (void)in_sizes; (void)n_in; (void)out_size;
    const float* x          = (const float*)d_in[0];
    const float* wqkv_w     = (const float*)d_in[3];
    const float* wqkv_b     = (const float*)d_in[4];
    const float* wp_w       = (const float*)d_in[5];
    const float* wp_b       = (const float*)d_in[6];
    const float* bias_table = (const float*)d_in[7];
    float* out = (float*)d_out;

    __half *wqh, *wph, *qkv_ptr, *yh;
    cudaGetSymbolAddress((void**)&wqh, g_wq);
    cudaGetSymbolAddress((void**)&wph, g_wp);
    cudaGetSymbolAddress((void**)&qkv_ptr, g_qkv);
    cudaGetSymbolAddress((void**)&yh, g_y);

    cudaFuncSetAttribute(gemm_mma_kernel<1, 1, 1>,
                         cudaFuncAttributeMaxDynamicSharedMemorySize, 3 * STAGE_B);
    cudaFuncSetAttribute(gemm_mma_kernel<0, 0, 0>,
                         cudaFuncAttributeMaxDynamicSharedMemorySize, 3 * STAGE_B);

    // 0) convert weights to fp16 (RN) — small
    cvt_half_kernel<<<256, 256>>>((const float4*)wqkv_w, (uint2*)wqh, QKV_DIM * CDIM / 4);
    cvt_half_kernel<<<128, 256>>>((const float4*)wp_w, (uint2*)wph, CDIM * CDIM / 4);

    // 1) QKV projection (fused x f32->f16) -> window-major fp16 qkv
    gemm_mma_kernel<1, 1, 1><<<dim3(QKV_DIM / 128, NTOK / 128), 256, 3 * STAGE_B>>>(
        x, wqh, wqkv_b, qkv_ptr, QKV_DIM);

    // 2) windowed attention (fp16 tensor cores)
    attn_kernel<<<dim3(NWIN, HEADS), 128>>>(qkv_ptr, bias_table, yh);

    // 3) output projection -> fp32 final output
    gemm_mma_kernel<0, 0, 0><<<dim3(CDIM / 128, NTOK / 128), 256, 3 * STAGE_B>>>(
        yh, wph, wp_b, out, CDIM);
}

// round 13
// speedup vs baseline: 1.1226x; 1.1226x over previous
#include <cuda_runtime.h>
#include <cuda_fp16.h>
#include <cstdint>

// ---------------------------------------------------------------------------
// SpatialWindowSelfAttention: b=2, img 256x256, C=256, 8 heads x 32, 8x8 windows
// Full fp16 pipeline (RN-rounded), fp32 accumulation, mma.sync m16n8k16.
// Attention keeps P entirely in registers (D-fragment == A-fragment layout).
// ---------------------------------------------------------------------------

#define IMG        256
#define BATCH      2
#define CDIM       256
#define NTOK       (BATCH * IMG * IMG)      // 131072
#define HEADS      8
#define HD         32
#define WS         64
#define NWIN       2048
#define QKV_DIM    (3 * CDIM)               // 768
#define GK         256

// Scratch (device globals; no allocs allowed)
__device__ __half g_x  [(size_t)NTOK * CDIM];
__device__ __half g_wq [(size_t)QKV_DIM * CDIM];
__device__ __half g_wp [(size_t)CDIM * CDIM];
__device__ __half g_qkv[(size_t)NTOK * QKV_DIM];  // [sel][head][win][tok][hd]
__device__ __half g_y  [(size_t)NTOK * CDIM];     // token-major

// ---------------------------------------------------------------------------
// helpers
// ---------------------------------------------------------------------------
__device__ __forceinline__ uint32_t smem_u32(const void* p) {
    uint32_t a;
    asm("{ .reg .u64 t; cvta.to.shared.u64 t, %1; cvt.u32.u64 %0, t; }" : "=r"(a) : "l"(p));
    return a;
}
__device__ __forceinline__ void cp16(uint32_t s, const void* g) {
    asm volatile("cp.async.cg.shared.global [%0], [%1], 16;\n" :: "r"(s), "l"(g) : "memory");
}
#define CP_COMMIT() asm volatile("cp.async.commit_group;\n" ::: "memory")
template <int N>
__device__ __forceinline__ void cp_wait() {
    asm volatile("cp.async.wait_group %0;\n" :: "n"(N) : "memory");
}
__device__ __forceinline__ void ldsm4(uint32_t& r0, uint32_t& r1, uint32_t& r2,
                                      uint32_t& r3, uint32_t addr) {
    asm volatile("ldmatrix.sync.aligned.m8n8.x4.shared.b16 {%0,%1,%2,%3}, [%4];"
                 : "=r"(r0), "=r"(r1), "=r"(r2), "=r"(r3) : "r"(addr));
}
__device__ __forceinline__ void ldsm4t(uint32_t& r0, uint32_t& r1, uint32_t& r2,
                                       uint32_t& r3, uint32_t addr) {
    asm volatile("ldmatrix.sync.aligned.m8n8.x4.trans.shared.b16 {%0,%1,%2,%3}, [%4];"
                 : "=r"(r0), "=r"(r1), "=r"(r2), "=r"(r3) : "r"(addr));
}
__device__ __forceinline__ void mma_f16(float* d, const uint32_t* a, const uint32_t* b) {
    asm volatile(
        "mma.sync.aligned.m16n8k16.row.col.f32.f16.f16.f32 "
        "{%0,%1,%2,%3},{%4,%5,%6,%7},{%8,%9},{%0,%1,%2,%3};"
        : "+f"(d[0]), "+f"(d[1]), "+f"(d[2]), "+f"(d[3])
        : "r"(a[0]), "r"(a[1]), "r"(a[2]), "r"(a[3]), "r"(b[0]), "r"(b[1]));
}
__device__ __forceinline__ uint32_t packh2(float x, float y) {
    const __half2 h = __floats2half2_rn(x, y);
    return *(const uint32_t*)&h;
}

// ---------------------------------------------------------------------------
// prep: convert f32 -> f16 (RN)
// ---------------------------------------------------------------------------
__global__ void cvt_half_kernel(const float4* __restrict__ src, uint2* __restrict__ dst, int n4)
{
    for (int i = blockIdx.x * blockDim.x + threadIdx.x; i < n4; i += gridDim.x * blockDim.x) {
        const float4 v = src[i];
        const __half2 h0 = __floats2half2_rn(v.x, v.y);
        const __half2 h1 = __floats2half2_rn(v.z, v.w);
        uint2 u;
        u.x = *(const uint32_t*)&h0;
        u.y = *(const uint32_t*)&h1;
        dst[i] = u;
    }
}

// ---------------------------------------------------------------------------
// fp16 GEMM: C[m][n] = sum_k A[m][k]*B[n][k] + bias[n], fp32 accum.
// 256 threads = 8 warps, 2m x 4n, warp tile 64x32. CTA tile 128x128.
// 3 smem buffers, 2 chunks in flight, one __syncthreads per chunk.
// OUTHALF: store __half (else float). SCATTER: window-major qkv scatter.
// ---------------------------------------------------------------------------
#define STAGE_B 32768
#define NCHUNK  4
template<int OUTHALF, int SCATTER>
__global__ void __launch_bounds__(256, 2)
gemm_mma_kernel(const __half* __restrict__ A,
                const __half* __restrict__ Bw,
                const float* __restrict__ bias,
                void* __restrict__ Cv, int N)
{
    extern __shared__ char sm[];
    const uint32_t sb = smem_u32(sm);

    const int tid  = threadIdx.x;
    const int lane = tid & 31;
    const int wid  = tid >> 5;
    const int g    = lane >> 2;
    const int t4   = lane & 3;
    const int wm   = (wid & 1) * 64;
    const int wn   = (wid >> 1) * 32;
    const int m0   = blockIdx.y * 128;
    const int n0   = blockIdx.x * 128;

    const char* Ag = (const char*)(A  + (size_t)m0 * GK);
    const char* Bg = (const char*)(Bw + (size_t)n0 * GK);

    float acc[4][4][4];
#pragma unroll
    for (int i = 0; i < 4; i++)
#pragma unroll
        for (int j = 0; j < 4; j++)
#pragma unroll
            for (int c = 0; c < 4; c++) acc[i][j][c] = 0.f;

    int rowA[4];
#pragma unroll
    for (int mf = 0; mf < 4; mf++) rowA[mf] = wm + mf * 16 + (lane & 15);
    const int haA = lane >> 4;
    int rowB[2];
#pragma unroll
    for (int p = 0; p < 2; p++) rowB[p] = wn + p * 16 + (lane & 7) + ((lane & 16) ? 8 : 0);
    const int haB = (lane >> 3) & 1;

    auto load_stage = [&](int it, int s) {
        const uint32_t sa = sb + (uint32_t)s * STAGE_B;
#pragma unroll
        for (int i = 0; i < 4; i++) {
            const int idx = tid + i * 256;
            const int row = idx >> 3, c = idx & 7;
            const uint32_t off = (uint32_t)(row * 128 + ((c ^ (row & 7)) << 4));
            const size_t goff = (size_t)row * (GK * 2) + it * 128 + c * 16;
            cp16(sa + off, Ag + goff);
            cp16(sa + 16384 + off, Bg + goff);
        }
        CP_COMMIT();
    };

    // 2 chunks in flight
    load_stage(0, 0);
    load_stage(1, 1);

#pragma unroll 1
    for (int it = 0; it < NCHUNK; it++) {
        if (it == NCHUNK - 1) cp_wait<0>();
        else                  cp_wait<1>();
        __syncthreads();     // chunk `it` resident

        if (it + 2 < NCHUNK) load_stage(it + 2, (it + 2) % 3);

        const uint32_t sa = sb + (uint32_t)(it % 3) * STAGE_B;
#pragma unroll
        for (int s = 0; s < 4; s++) {          // 4 x k16 steps per 64-half chunk
            uint32_t a[4][4], b[4][2];
#pragma unroll
            for (int mf = 0; mf < 4; mf++) {
                const int r = rowA[mf];
                ldsm4(a[mf][0], a[mf][1], a[mf][2], a[mf][3],
                      sa + r * 128 + (((2 * s + haA) ^ (r & 7)) << 4));
            }
#pragma unroll
            for (int p = 0; p < 2; p++) {
                const int r = rowB[p];
                uint32_t r0, r1, r2, r3;
                ldsm4(r0, r1, r2, r3,
                      sa + 16384 + r * 128 + (((2 * s + haB) ^ (r & 7)) << 4));
                b[2 * p][0] = r0; b[2 * p][1] = r1;
                b[2 * p + 1][0] = r2; b[2 * p + 1][1] = r3;
            }
#pragma unroll
            for (int mf = 0; mf < 4; mf++)
#pragma unroll
                for (int nf = 0; nf < 4; nf++)
                    mma_f16(acc[mf][nf], a[mf], b[nf]);
        }
    }

    // epilogue
#pragma unroll
    for (int mf = 0; mf < 4; mf++) {
        const int r0 = m0 + wm + mf * 16 + g;
        const int r1 = r0 + 8;
        size_t tb0 = 0, tb1 = 0;
        if (SCATTER) {
            const int bb0 = r0 >> 16, px0 = r0 & 65535;
            const int win0 = bb0 * 1024 + ((px0 >> 8) >> 3) * 32 + ((px0 & 255) >> 3);
            const int tk0  = (((px0 >> 8) & 7) << 3) + (px0 & 7);
            tb0 = (size_t)win0 * (WS * HD) + tk0 * HD;
            const int bb1 = r1 >> 16, px1 = r1 & 65535;
            const int win1 = bb1 * 1024 + ((px1 >> 8) >> 3) * 32 + ((px1 & 255) >> 3);
            const int tk1  = (((px1 >> 8) & 7) << 3) + (px1 & 7);
            tb1 = (size_t)win1 * (WS * HD) + tk1 * HD;
        }
#pragma unroll
        for (int nf = 0; nf < 4; nf++) {
            const int col = n0 + wn + nf * 8 + 2 * t4;
            const float2 bv = *(const float2*)&bias[col];
            float2 o0, o1;
            o0.x = acc[mf][nf][0] + bv.x;
            o0.y = acc[mf][nf][1] + bv.y;
            o1.x = acc[mf][nf][2] + bv.x;
            o1.y = acc[mf][nf][3] + bv.y;
            if (OUTHALF) {
                __half* C = (__half*)Cv;
                const __half2 h0 = __floats2half2_rn(o0.x, o0.y);
                const __half2 h1 = __floats2half2_rn(o1.x, o1.y);
                if (SCATTER) {
                    const size_t ch = (size_t)(col >> 5) * ((size_t)NWIN * WS * HD) + (col & 31);
                    *(__half2*)&C[ch + tb0] = h0;
                    *(__half2*)&C[ch + tb1] = h1;
                } else {
                    *(__half2*)&C[(size_t)r0 * N + col] = h0;
                    *(__half2*)&C[(size_t)r1 * N + col] = h1;
                }
            } else {
                float* C = (float*)Cv;
                *(float2*)&C[(size_t)r0 * N + col] = o0;
                *(float2*)&C[(size_t)r1 * N + col] = o1;
            }
        }
    }
}

// ---------------------------------------------------------------------------
// Window attention, fp16 tensor cores. Block = (window, head), 128 thr, 4 warps.
// smem (~16.3KB): qs/ks/vs 80B-pitch rows + bias table. ONE barrier total.
// P stays in registers: QK^T D-fragment == PV A-fragment layout.
// ---------------------------------------------------------------------------
__global__ __launch_bounds__(128, 8)
void attn_kernel(const __half* __restrict__ qkv,
                 const float* __restrict__ bias_table,
                 __half* __restrict__ y)
{
    __shared__ __align__(16) char sraw[15360 + 912];
    const uint32_t base = smem_u32(sraw);
    const uint32_t qsb = base;
    const uint32_t ksb = base + 5120;
    const uint32_t vsb = base + 10240;
    float* bt = (float*)(sraw + 15360);

    const int tid  = threadIdx.x;
    const int lane = tid & 31;
    const int wid  = tid >> 5;
    const int g    = lane >> 2;
    const int t4   = lane & 3;
    const int win  = blockIdx.x;
    const int hh   = blockIdx.y;

    const __half* qg = qkv + ((size_t)(0 * HEADS + hh) * NWIN + win) * (WS * HD);
    const __half* kg = qkv + ((size_t)(1 * HEADS + hh) * NWIN + win) * (WS * HD);
    const __half* vg = qkv + ((size_t)(2 * HEADS + hh) * NWIN + win) * (WS * HD);

#pragma unroll
    for (int i = 0; i < 6; i++) {
        const int idx = tid + i * 128;
        const int sel = idx >> 8;           // 0=q,1=k,2=v
        const int rem = idx & 255;
        const int t   = rem >> 2;
        const int c   = rem & 3;
        const __half* src = (sel == 0 ? qg : sel == 1 ? kg : vg) + t * HD + c * 8;
        const uint32_t dstb = (sel == 0 ? qsb : sel == 1 ? ksb : vsb);
        cp16(dstb + t * 80 + c * 16, src);
    }
    CP_COMMIT();

    for (int i = tid; i < 225; i += 128) bt[i] = bias_table[i * HEADS + hh];
    cp_wait<0>();
    __syncthreads();

    // ---- QK^T: warp owns q-rows [wid*16, +16); 64 keys in regs ----
    float s[8][4];
#pragma unroll
    for (int j = 0; j < 8; j++)
#pragma unroll
        for (int c = 0; c < 4; c++) s[j][c] = 0.f;

    const int rA  = wid * 16 + (lane & 15);
    const int haA = lane >> 4;
    const int haB = (lane >> 3) & 1;

#pragma unroll
    for (int s2 = 0; s2 < 2; s2++) {
        uint32_t a[4];
        ldsm4(a[0], a[1], a[2], a[3], qsb + rA * 80 + (2 * s2 + haA) * 16);
#pragma unroll
        for (int p = 0; p < 4; p++) {
            const int r = p * 16 + (lane & 7) + ((lane & 16) ? 8 : 0);
            uint32_t b0, b1, b2, b3;
            ldsm4(b0, b1, b2, b3, ksb + r * 80 + (2 * s2 + haB) * 16);
            uint32_t bA[2] = {b0, b1}, bB[2] = {b2, b3};
            mma_f16(s[2 * p], a, bA);
            mma_f16(s[2 * p + 1], a, bB);
        }
    }

    // ---- scale + bias + softmax in regs (reduce across t4 quad) ----
    const float scale = 0.17677669529663687f;
    const int qlo = wid * 16 + g;
    const int qhi = qlo + 8;
    const int qi0 = qlo >> 3, qj0 = qlo & 7;
    const int qi1 = qhi >> 3, qj1 = qhi & 7;

    float mlo = -1e30f, mhi = -1e30f;
#pragma unroll
    for (int j = 0; j < 8; j++) {
        const int c0 = j * 8 + 2 * t4, c1 = c0 + 1;
        const int ki0 = c0 >> 3, kj0 = c0 & 7;
        const int ki1 = c1 >> 3, kj1 = c1 & 7;
        s[j][0] = s[j][0] * scale + bt[(qi0 - ki0 + 7) * 15 + (qj0 - kj0 + 7)];
        s[j][1] = s[j][1] * scale + bt[(qi0 - ki1 + 7) * 15 + (qj0 - kj1 + 7)];
        s[j][2] = s[j][2] * scale + bt[(qi1 - ki0 + 7) * 15 + (qj1 - kj0 + 7)];
        s[j][3] = s[j][3] * scale + bt[(qi1 - ki1 + 7) * 15 + (qj1 - kj1 + 7)];
        mlo = fmaxf(mlo, fmaxf(s[j][0], s[j][1]));
        mhi = fmaxf(mhi, fmaxf(s[j][2], s[j][3]));
    }
    mlo = fmaxf(mlo, __shfl_xor_sync(0xffffffffu, mlo, 1));
    mlo = fmaxf(mlo, __shfl_xor_sync(0xffffffffu, mlo, 2));
    mhi = fmaxf(mhi, __shfl_xor_sync(0xffffffffu, mhi, 1));
    mhi = fmaxf(mhi, __shfl_xor_sync(0xffffffffu, mhi, 2));

    float slo = 0.f, shi = 0.f;
#pragma unroll
    for (int j = 0; j < 8; j++) {
        s[j][0] = __expf(s[j][0] - mlo);
        s[j][1] = __expf(s[j][1] - mlo);
        s[j][2] = __expf(s[j][2] - mhi);
        s[j][3] = __expf(s[j][3] - mhi);
        slo += s[j][0] + s[j][1];
        shi += s[j][2] + s[j][3];
    }
    slo += __shfl_xor_sync(0xffffffffu, slo, 1);
    slo += __shfl_xor_sync(0xffffffffu, slo, 2);
    shi += __shfl_xor_sync(0xffffffffu, shi, 1);
    shi += __shfl_xor_sync(0xffffffffu, shi, 2);
    const float ilo = 1.f / slo, ihi = 1.f / shi;

    // ---- PV: A = P packed straight from registers; B = V ldmatrix.trans ----
    // QK D-fragment (lane g,t4; n-tile j keys 8j+2t4,+1; rows qlo/qhi) maps
    // exactly onto the m16n8k16 A-fragment for k-step s2 (k = keys 16s2..+15):
    //   a0 = (qlo, 16s2+2t4,+1)   = s[2s2][0..1]
    //   a1 = (qhi, ...)           = s[2s2][2..3]
    //   a2 = (qlo, 16s2+8+2t4,+1) = s[2s2+1][0..1]
    //   a3 = (qhi, ...)           = s[2s2+1][2..3]
    float o[4][4];
#pragma unroll
    for (int j = 0; j < 4; j++)
#pragma unroll
        for (int c = 0; c < 4; c++) o[j][c] = 0.f;

#pragma unroll
    for (int s2 = 0; s2 < 4; s2++) {
        uint32_t a[4];
        a[0] = packh2(s[2 * s2][0] * ilo,     s[2 * s2][1] * ilo);
        a[1] = packh2(s[2 * s2][2] * ihi,     s[2 * s2][3] * ihi);
        a[2] = packh2(s[2 * s2 + 1][0] * ilo, s[2 * s2 + 1][1] * ilo);
        a[3] = packh2(s[2 * s2 + 1][2] * ihi, s[2 * s2 + 1][3] * ihi);
#pragma unroll
        for (int p = 0; p < 2; p++) {
            const int key = 16 * s2 + (lane & 7) + ((lane & 8) ? 8 : 0);
            const int chk = 2 * p + ((lane & 16) ? 1 : 0);
            uint32_t r0, r1, r2, r3;
            ldsm4t(r0, r1, r2, r3, vsb + key * 80 + chk * 16);
            uint32_t bA[2] = {r0, r1}, bB[2] = {r2, r3};
            mma_f16(o[2 * p], a, bA);
            mma_f16(o[2 * p + 1], a, bB);
        }
    }

    // ---- write y (fp16, token-major) ----
    {
        const int bb = win >> 10;
        const int wr = (win >> 5) & 31;
        const int wc = win & 31;
#pragma unroll
        for (int rr = 0; rr < 2; rr++) {
            const int qr = wid * 16 + g + rr * 8;
            const int trw = qr >> 3, tcl = qr & 7;
            const size_t tok = (size_t)bb * (IMG * IMG)
                             + (size_t)(wr * 8 + trw) * IMG + (wc * 8 + tcl);
            __half* dst = &y[tok * CDIM + hh * HD];
#pragma unroll
            for (int j = 0; j < 4; j++) {
                const int col = j * 8 + 2 * t4;
                const __half2 hv = __floats2half2_rn(o[j][rr * 2 + 0], o[j][rr * 2 + 1]);
                *(__half2*)&dst[col] = hv;
            }
        }
    }
}

// ---------------------------------------------------------------------------
extern "C" void kernel_launch(void* const* d_in, const int* in_sizes, int n_in,
                              void* d_out, int out_size)
{
    (void)in_sizes; (void)n_in; (void)out_size;
    const float* x          = (const float*)d_in[0];
    const float* wqkv_w     = (const float*)d_in[3];
    const float* wqkv_b     = (const float*)d_in[4];
    const float* wp_w       = (const float*)d_in[5];
    const float* wp_b       = (const float*)d_in[6];
    const float* bias_table = (const float*)d_in[7];
    float* out = (float*)d_out;

    __half *xh, *wqh, *wph, *qkv_ptr, *yh;
    cudaGetSymbolAddress((void**)&xh, g_x);
    cudaGetSymbolAddress((void**)&wqh, g_wq);
    cudaGetSymbolAddress((void**)&wph, g_wp);
    cudaGetSymbolAddress((void**)&qkv_ptr, g_qkv);
    cudaGetSymbolAddress((void**)&yh, g_y);

    cudaFuncSetAttribute(gemm_mma_kernel<1, 1>,
                         cudaFuncAttributeMaxDynamicSharedMemorySize, 3 * STAGE_B);
    cudaFuncSetAttribute(gemm_mma_kernel<0, 0>,
                         cudaFuncAttributeMaxDynamicSharedMemorySize, 3 * STAGE_B);

    // 0) convert inputs to fp16 (RN)
    cvt_half_kernel<<<4096, 256>>>((const float4*)x, (uint2*)xh, NTOK * CDIM / 4);
    cvt_half_kernel<<<256, 256>>>((const float4*)wqkv_w, (uint2*)wqh, QKV_DIM * CDIM / 4);
    cvt_half_kernel<<<128, 256>>>((const float4*)wp_w, (uint2*)wph, CDIM * CDIM / 4);

    // 1) QKV projection -> window-major fp16 qkv
    gemm_mma_kernel<1, 1><<<dim3(QKV_DIM / 128, NTOK / 128), 256, 3 * STAGE_B>>>(
        xh, wqh, wqkv_b, qkv_ptr, QKV_DIM);

    // 2) windowed attention (fp16 tensor cores, P in registers)
    attn_kernel<<<dim3(NWIN, HEADS), 128>>>(qkv_ptr, bias_table, yh);

    // 3) output projection -> fp32 final output
    gemm_mma_kernel<0, 0><<<dim3(CDIM / 128, NTOK / 128), 256, 3 * STAGE_B>>>(
        yh, wph, wp_b, out, CDIM);
}